// round 10
// baseline (speedup 1.0000x reference)
#include <cuda_runtime.h>
#include <math.h>
#include <stdint.h>

// ===========================================================================
// Scratch (device globals — allocation-free per harness rules)
// ===========================================================================
#define MAXN 20000
#define MAXD 1000
#define MAXDA 128

__device__ float g_sup [(size_t)MAXN * MAXD];   // 80 MB
__device__ float g_agg [(size_t)MAXN * MAXD];   // 80 MB
__device__ float g_supA[(size_t)MAXN * MAXDA];  // 10 MB
__device__ float g_aggA[(size_t)MAXN * MAXDA];  // 10 MB

// ===========================================================================
// Helpers
// ===========================================================================
__device__ __forceinline__ uint32_t tf32_hi_bits(float x) {
    return __float_as_uint(x) & 0xFFFFE000u;
}

__device__ __forceinline__ void mma_tf32(float* c, const uint32_t* a, const uint32_t* b) {
    asm volatile(
        "mma.sync.aligned.m16n8k8.row.col.f32.tf32.tf32.f32 "
        "{%0,%1,%2,%3}, {%4,%5,%6,%7}, {%8,%9}, {%0,%1,%2,%3};"
        : "+f"(c[0]), "+f"(c[1]), "+f"(c[2]), "+f"(c[3])
        : "r"(a[0]), "r"(a[1]), "r"(a[2]), "r"(a[3]),
          "r"(b[0]), "r"(b[1]));
}

__device__ __forceinline__ float4 ldg4_guard(const float* __restrict__ p,
                                             int r, int c, int R, int C) {
    float4 v = make_float4(0.f, 0.f, 0.f, 0.f);
    if (r < R) {
        if (c + 3 < C) {
            v = *reinterpret_cast<const float4*>(p + (size_t)r * C + c);
        } else {
            if (c + 0 < C) v.x = p[(size_t)r * C + c + 0];
            if (c + 1 < C) v.y = p[(size_t)r * C + c + 1];
            if (c + 2 < C) v.z = p[(size_t)r * C + c + 2];
            if (c + 3 < C) v.w = p[(size_t)r * C + c + 3];
        }
    }
    return v;
}

__device__ __forceinline__ void red_add_v4(float* p, float a, float b, float c, float d) {
    asm volatile("red.global.add.v4.f32 [%0], {%1, %2, %3, %4};"
                 :: "l"(p), "f"(a), "f"(b), "f"(c), "f"(d) : "memory");
}

// ===========================================================================
// Warp-MMA TF32x2-split GEMM:  C[M,N] = op(A)[M,K] @ B[K,N]
//   CTA tile 128 x BN (BN=256 structural / 128 attr), BK=16, 256 threads,
//   8 warps (2 x 4), warp tile 64 x (BN/4). Raw fp32 tiles in smem
//   (double-buffered, dynamic); tf32 hi/lo mask-split at fragment load.
//   Strides 136 / BN+8  ==> 8 mod 32: all LDS/STS provably conflict-free.
//   Products: Ah*Bh + Ah*Bl + Al*Bh (rel err ~2^-22).
// ===========================================================================
#define AST 136   // A smem row stride (floats), 136 mod 32 = 8

template<int BN>
static constexpr int gemm_smem_bytes() {
    return (2 * 16 * AST + 2 * 16 * (BN + 8)) * 4;
}

template<bool RELU_A, int BN>
__global__ __launch_bounds__(256)
void gemm_mma(const float* __restrict__ A, const float* __restrict__ B,
              float* __restrict__ C, int M, int N, int K)
{
    constexpr int BST = BN + 8;       // B smem row stride, mod 32 = 8
    constexpr int NI  = BN / 32;      // per-warp 8-wide n tiles (8 or 4)
    constexpr int NH  = NI / 4;       // n-tile halves (2 or 1)
    constexpr int BPT = BN / 64;      // B float4 loads per thread (4 or 2)

    extern __shared__ float smem[];
    float* Asm = smem;                        // [2][16][AST]
    float* Bsm = smem + 2 * 16 * AST;         // [2][16][BST]
#define AS(b, k, m) Asm[((b) * 16 + (k)) * AST + (m)]
#define BS(b, k, n) Bsm[((b) * 16 + (k)) * BST + (n)]

    const int tid  = threadIdx.x;
    const int wid  = tid >> 5;
    const int lane = tid & 31;
    const int g    = lane >> 2;          // groupID 0..7
    const int tig  = lane & 3;           // thread-in-group 0..3
    const int warp_m = wid >> 2;         // 0..1  (64 rows each)
    const int warp_n = wid & 3;          // 0..3  (BN/4 cols each)
    const int m0 = blockIdx.y * 128;
    const int n0 = blockIdx.x * BN;

    // loader mappings (conflict-free STS, coalesced LDG)
    const int ar  = tid & 127;           // A row 0..127 (lane-consecutive)
    const int akq = (tid >> 7) * 8;      // A k-offset 0/8
    const int bkr = tid >> 4;            // B k-row 0..15
    const int bq0 = (tid & 15) * 4;      // B col base (float4, lane-consecutive)

    float acc[4][NI][4];
#pragma unroll
    for (int i = 0; i < 4; i++)
#pragma unroll
        for (int j = 0; j < NI; j++)
#pragma unroll
            for (int q = 0; q < 4; q++) acc[i][j][q] = 0.f;

    const int nkt = (K + 15) >> 4;

    float4 aR[2], bR[BPT];
    // load tile 0
    aR[0] = ldg4_guard(A, m0 + ar, akq,     M, K);
    aR[1] = ldg4_guard(A, m0 + ar, akq + 4, M, K);
#pragma unroll
    for (int j = 0; j < BPT; j++)
        bR[j] = ldg4_guard(B, bkr, n0 + bq0 + 64 * j, K, N);
    // stage tile 0 into buffer 0
    {
        float av[8] = {aR[0].x, aR[0].y, aR[0].z, aR[0].w,
                       aR[1].x, aR[1].y, aR[1].z, aR[1].w};
#pragma unroll
        for (int j = 0; j < 8; j++)
            AS(0, akq + j, ar) = RELU_A ? fmaxf(av[j], 0.f) : av[j];
#pragma unroll
        for (int j = 0; j < BPT; j++)
            *reinterpret_cast<float4*>(&BS(0, bkr, bq0 + 64 * j)) = bR[j];
    }
    __syncthreads();

    for (int kt = 0; kt < nkt; kt++) {
        const int cur = kt & 1;
        const bool more = (kt + 1 < nkt);

        // ---- global prefetch for tile kt+1 (overlaps MMA below) ----
        if (more) {
            const int kb = (kt + 1) * 16;
            aR[0] = ldg4_guard(A, m0 + ar,  kb + akq,     M, K);
            aR[1] = ldg4_guard(A, m0 + ar,  kb + akq + 4, M, K);
#pragma unroll
            for (int j = 0; j < BPT; j++)
                bR[j] = ldg4_guard(B, kb + bkr, n0 + bq0 + 64 * j, K, N);
        }

        // ---- MMA over two k=8 steps ----
#pragma unroll
        for (int ks = 0; ks < 2; ks++) {
            const int kk = ks * 8;
            uint32_t ah[4][4], al[4][4];
#pragma unroll
            for (int mi = 0; mi < 4; mi++) {
                const int m = warp_m * 64 + mi * 16 + g;
                float x0 = AS(cur, kk + tig,     m);
                float x1 = AS(cur, kk + tig,     m + 8);
                float x2 = AS(cur, kk + tig + 4, m);
                float x3 = AS(cur, kk + tig + 4, m + 8);
                uint32_t h0 = tf32_hi_bits(x0), h1 = tf32_hi_bits(x1);
                uint32_t h2 = tf32_hi_bits(x2), h3 = tf32_hi_bits(x3);
                ah[mi][0] = h0; al[mi][0] = __float_as_uint(x0 - __uint_as_float(h0));
                ah[mi][1] = h1; al[mi][1] = __float_as_uint(x1 - __uint_as_float(h1));
                ah[mi][2] = h2; al[mi][2] = __float_as_uint(x2 - __uint_as_float(h2));
                ah[mi][3] = h3; al[mi][3] = __float_as_uint(x3 - __uint_as_float(h3));
            }
            // process n tiles in halves of 4 to cap live registers
#pragma unroll
            for (int h = 0; h < NH; h++) {
                uint32_t bh[4][2], bl[4][2];
#pragma unroll
                for (int nj = 0; nj < 4; nj++) {
                    const int n = warp_n * (BN / 4) + (h * 4 + nj) * 8 + g;
                    float y0 = BS(cur, kk + tig,     n);
                    float y1 = BS(cur, kk + tig + 4, n);
                    uint32_t h0 = tf32_hi_bits(y0), h1 = tf32_hi_bits(y1);
                    bh[nj][0] = h0; bl[nj][0] = __float_as_uint(y0 - __uint_as_float(h0));
                    bh[nj][1] = h1; bl[nj][1] = __float_as_uint(y1 - __uint_as_float(h1));
                }
                // product-major order: independent accumulators back-to-back
#pragma unroll
                for (int mi = 0; mi < 4; mi++)
#pragma unroll
                    for (int nj = 0; nj < 4; nj++)
                        mma_tf32(acc[mi][h * 4 + nj], ah[mi], bh[nj]);
#pragma unroll
                for (int mi = 0; mi < 4; mi++)
#pragma unroll
                    for (int nj = 0; nj < 4; nj++)
                        mma_tf32(acc[mi][h * 4 + nj], ah[mi], bl[nj]);
#pragma unroll
                for (int mi = 0; mi < 4; mi++)
#pragma unroll
                    for (int nj = 0; nj < 4; nj++)
                        mma_tf32(acc[mi][h * 4 + nj], al[mi], bh[nj]);
            }
        }

        // ---- stage tile kt+1 into the other buffer ----
        if (more) {
            const int nxt = cur ^ 1;
            float av[8] = {aR[0].x, aR[0].y, aR[0].z, aR[0].w,
                           aR[1].x, aR[1].y, aR[1].z, aR[1].w};
#pragma unroll
            for (int j = 0; j < 8; j++)
                AS(nxt, akq + j, ar) = RELU_A ? fmaxf(av[j], 0.f) : av[j];
#pragma unroll
            for (int j = 0; j < BPT; j++)
                *reinterpret_cast<float4*>(&BS(nxt, bkr, bq0 + 64 * j)) = bR[j];
        }
        __syncthreads();
    }

    // ---- epilogue ----
#pragma unroll
    for (int mi = 0; mi < 4; mi++) {
#pragma unroll
        for (int ni = 0; ni < NI; ni++) {
            const int r  = m0 + warp_m * 64 + mi * 16 + g;
            const int cc = n0 + warp_n * (BN / 4) + ni * 8 + 2 * tig;
            if (cc + 1 < N) {
                if (r < M)
                    *reinterpret_cast<float2*>(C + (size_t)r * N + cc) =
                        make_float2(acc[mi][ni][0], acc[mi][ni][1]);
                if (r + 8 < M)
                    *reinterpret_cast<float2*>(C + (size_t)(r + 8) * N + cc) =
                        make_float2(acc[mi][ni][2], acc[mi][ni][3]);
            } else if (cc < N) {
                if (r < M)     C[(size_t)r * N + cc]       = acc[mi][ni][0];
                if (r + 8 < M) C[(size_t)(r + 8) * N + cc] = acc[mi][ni][2];
            }
        }
    }
#undef AS
#undef BS
}

// ===========================================================================
// Zero kernel (vector stores, grid-stride)
// ===========================================================================
__global__ void zero_kernel(float4* __restrict__ p, int n4) {
    int i = blockIdx.x * blockDim.x + threadIdx.x;
    int stride = gridDim.x * blockDim.x;
    float4 z = make_float4(0.f, 0.f, 0.f, 0.f);
    for (; i < n4; i += stride) p[i] = z;
}

// ===========================================================================
// SpMM (COO, vector-red scatter):  out[row[e], :] += vals[e] * sup[col[e], :]
// ===========================================================================
__global__ __launch_bounds__(256) void spmm_wide(
    const int* __restrict__ row, const int* __restrict__ col,
    const float* __restrict__ vals, const float* __restrict__ sup,
    float* __restrict__ out, int D)
{
    int e = blockIdx.x;
    int r = __ldg(row + e);
    int c = __ldg(col + e);
    float v = __ldg(vals + e);
    const float4* s = reinterpret_cast<const float4*>(sup + (size_t)c * D);
    float* o = out + (size_t)r * D;
    int nd4 = D >> 2;
    for (int t = threadIdx.x; t < nd4; t += blockDim.x) {
        float4 x = __ldg(s + t);
        red_add_v4(o + 4 * t, v * x.x, v * x.y, v * x.z, v * x.w);
    }
}

__global__ __launch_bounds__(256) void spmm_narrow(
    const int* __restrict__ row, const int* __restrict__ col,
    const float* __restrict__ vals, const float* __restrict__ sup,
    float* __restrict__ out, int D, int E)
{
    int e = blockIdx.x * (blockDim.x >> 5) + (threadIdx.x >> 5);
    if (e >= E) return;
    int lane = threadIdx.x & 31;
    int r = __ldg(row + e);
    int c = __ldg(col + e);
    float v = __ldg(vals + e);
    const float4* s = reinterpret_cast<const float4*>(sup + (size_t)c * D);
    float* o = out + (size_t)r * D;
    int nd4 = D >> 2;
    for (int t = lane; t < nd4; t += 32) {
        float4 x = __ldg(s + t);
        red_add_v4(o + 4 * t, v * x.x, v * x.y, v * x.z, v * x.w);
    }
}

// ===========================================================================
// Fused relu + row L2-normalize
// ===========================================================================
__global__ __launch_bounds__(256) void l2norm_relu(
    const float* __restrict__ in, float* __restrict__ out, int D)
{
    int r = blockIdx.x;
    const float* x = in + (size_t)r * D;
    float* o = out + (size_t)r * D;

    float s = 0.f;
    for (int t = threadIdx.x; t < D; t += blockDim.x) {
        float v = fmaxf(x[t], 0.f);
        s += v * v;
    }
#pragma unroll
    for (int off = 16; off > 0; off >>= 1)
        s += __shfl_xor_sync(0xFFFFFFFFu, s, off);
    __shared__ float red[8];
    int wid = threadIdx.x >> 5;
    if ((threadIdx.x & 31) == 0) red[wid] = s;
    __syncthreads();
    if (threadIdx.x < 8) {
        float t = red[threadIdx.x];
#pragma unroll
        for (int off = 4; off > 0; off >>= 1)
            t += __shfl_xor_sync(0xFFu, t, off);
        if (threadIdx.x == 0) red[0] = t;
    }
    __syncthreads();
    float inv = 1.f / fmaxf(sqrtf(red[0]), 1e-12f);
    for (int t = threadIdx.x; t < D; t += blockDim.x)
        o[t] = fmaxf(x[t], 0.f) * inv;
}

__global__ void relu_copy(const float* __restrict__ in, float* __restrict__ out, int n) {
    int i = blockIdx.x * blockDim.x + threadIdx.x;
    int stride = gridDim.x * blockDim.x;
    for (; i < n; i += stride) out[i] = fmaxf(in[i], 0.f);
}

// ===========================================================================
// Host-side pipeline
// ===========================================================================
static inline int cdiv(int a, int b) { return (a + b - 1) / b; }
static inline int isqrt_i(int v) { return (int)floor(sqrt((double)v) + 0.5); }

template<int BN>
static void run_gemm(const float* A, const float* B, float* C,
                     int M, int N, int K, bool reluA)
{
    dim3 grid(cdiv(N, BN), cdiv(M, 128));
    const int smem = gemm_smem_bytes<BN>();
    if (reluA) gemm_mma<true , BN><<<grid, 256, smem>>>(A, B, C, M, N, K);
    else       gemm_mma<false, BN><<<grid, 256, smem>>>(A, B, C, M, N, K);
}

static void zero_buf(float* p, size_t n) {
    int n4 = (int)(n / 4);
    zero_kernel<<<1024, 256>>>(reinterpret_cast<float4*>(p), n4);
}

extern "C" void kernel_launch(void* const* d_in, const int* in_sizes, int n_in,
                              void* d_out, int out_size)
{
    const float* emb_sr  = (const float*)d_in[0];
    const float* emb_tg  = (const float*)d_in[1];
    const float* attr_sr = (const float*)d_in[2];
    const float* attr_tg = (const float*)d_in[3];
    const int*   row_sr  = (const int*)  d_in[4];
    const int*   col_sr  = (const int*)  d_in[5];
    const float* vals_sr = (const float*)d_in[6];
    const int*   row_tg  = (const int*)  d_in[7];
    const int*   col_tg  = (const int*)  d_in[8];
    const float* vals_tg = (const float*)d_in[9];
    const float* W_s0    = (const float*)d_in[10];
    const float* W_s1    = (const float*)d_in[11];
    const float* W_a11   = (const float*)d_in[12];
    const float* W_a12   = (const float*)d_in[13];
    const float* W_a2    = (const float*)d_in[14];

    const int D  = isqrt_i(in_sizes[10]);          // 1000
    const int Da = isqrt_i(in_sizes[14]);          // 100
    const int A  = in_sizes[12] / Da;              // 1000
    const int N  = in_sizes[0] / D;                // 20000
    const int M  = in_sizes[1] / D;                // 20000
    const int E1 = in_sizes[4];                    // 160000
    const int E2 = in_sizes[7];

    // allow >48KB dynamic smem for the BN=256 instantiations (idempotent)
    cudaFuncSetAttribute((const void*)gemm_mma<true , 256>,
                         cudaFuncAttributeMaxDynamicSharedMemorySize, gemm_smem_bytes<256>());
    cudaFuncSetAttribute((const void*)gemm_mma<false, 256>,
                         cudaFuncAttributeMaxDynamicSharedMemorySize, gemm_smem_bytes<256>());

    float* sup;  cudaGetSymbolAddress((void**)&sup,  g_sup);
    float* agg;  cudaGetSymbolAddress((void**)&agg,  g_agg);
    float* supA; cudaGetSymbolAddress((void**)&supA, g_supA);
    float* aggA; cudaGetSymbolAddress((void**)&aggA, g_aggA);

    float* out = (float*)d_out;
    float* out_sr  = out;
    float* out_tg  = out + (size_t)N * D;
    float* out_sra = out + (size_t)(N + M) * D;
    float* out_tga = out_sra + (size_t)N * Da;

    // ---------------- structural branch (shared weights W_s0, W_s1) --------
    for (int g = 0; g < 2; g++) {
        const float* emb  = g ? emb_tg : emb_sr;
        const int*   row  = g ? row_tg : row_sr;
        const int*   col  = g ? col_tg : col_sr;
        const float* vals = g ? vals_tg : vals_sr;
        const int    E    = g ? E2 : E1;
        const int    Nn   = g ? M : N;
        float*       op   = g ? out_tg : out_sr;

        // layer 1
        run_gemm<256>(emb, W_s0, sup, Nn, D, D, false);
        zero_buf(agg, (size_t)Nn * D);
        spmm_wide<<<E, 256>>>(row, col, vals, sup, agg, D);
        // layer 2 (relu fused into A-tile load)
        run_gemm<256>(agg, W_s1, sup, Nn, D, D, true);
        zero_buf(agg, (size_t)Nn * D);
        spmm_wide<<<E, 256>>>(row, col, vals, sup, agg, D);
        // relu + l2norm to output
        l2norm_relu<<<Nn, 256>>>(agg, op, D);
    }

    // ---------------- attribute branch ------------------------------------
    for (int g = 0; g < 2; g++) {
        const float* attr = g ? attr_tg : attr_sr;
        const float* Wa1  = g ? W_a12 : W_a11;
        const int*   row  = g ? row_tg : row_sr;
        const int*   col  = g ? col_tg : col_sr;
        const float* vals = g ? vals_tg : vals_sr;
        const int    E    = g ? E2 : E1;
        const int    Nn   = g ? M : N;
        float*       op   = g ? out_tga : out_sra;

        // layer 1: attr[Nn,A] @ Wa1[A,Da]
        run_gemm<128>(attr, Wa1, supA, Nn, Da, A, false);
        zero_buf(aggA, (size_t)Nn * Da);
        spmm_narrow<<<cdiv(E, 8), 256>>>(row, col, vals, supA, aggA, Da, E);
        // layer 2: relu(agg) @ W_a2[Da,Da]
        run_gemm<128>(aggA, W_a2, supA, Nn, Da, Da, true);
        zero_buf(aggA, (size_t)Nn * Da);
        spmm_narrow<<<cdiv(E, 8), 256>>>(row, col, vals, supA, aggA, Da, E);
        // final relu to output
        relu_copy<<<1024, 256>>>(aggA, op, Nn * Da);
    }
}